// round 14
// baseline (speedup 1.0000x reference)
// Fused gather+concat -> Linear(256,1024) -> GELU -> Linear(1024,2)
// sm_100 legacy mma.sync fp16 m16n8k16, 2 CTAs/SM.
// R12 resubmit (container infra flake; R5/R7/R10 precedent: identical source
// passed on retry).
// fp16 C-fragments (2 regs/tile vs 4) -> warp tile 32x64 at the same 32
// accumulator regs -> NGROUPS 16->8, A smem re-reads halved (LDS 4.5->3.5MB/CTA).
// B stream in K=32 blocks (8KB) through the same 3-slot single-barrier ring.
// Bias+GELU+W2 still fp32 in epilogue.

#include <cuda_runtime.h>
#include <cuda_fp16.h>
#include <cstdint>

#define NTHREADS   256
#define TILE_M     128
#define NGROUPS    8           // 1024 / 128
#define NKB        8           // K blocks per group-sweep: 8 x 32 = 256
#define NBLOCKS    64          // ngroups * nkb, linear B stream
#define BBLK_BYTES 8192        // 32 K x 128 cols x 2B

// smem layout (bytes)
#define OFF_IDX    0           // 256 ints
#define OFF_CMB    1024        // 128 float2
#define OFF_B1     2048        // 1024 f32
#define OFF_W2     6144        // 1024 float2
#define OFF_A      14336       // A frags: 16 ksteps x 8 mtiles x 32 lanes x 16B = 65536
#define OFF_B      79872       // 3 x 8KB B ring slots
#define SMEM_BYTES 104448

// ---------------- helpers ----------------
__device__ __forceinline__ uint32_t smem_u32(const void* p) {
    uint32_t a;
    asm("{ .reg .u64 t; cvta.to.shared.u64 t, %1; cvt.u32.u64 %0, t; }"
        : "=r"(a) : "l"(p));
    return a;
}

#define CP_ASYNC16(dst, src) \
    asm volatile("cp.async.cg.shared.global [%0], [%1], 16;" :: "r"(dst), "l"(src))
#define CP_COMMIT() asm volatile("cp.async.commit_group;" ::: "memory")
#define CP_WAIT(n)  asm volatile("cp.async.wait_group %0;" :: "n"(n) : "memory")

// pack two f32 -> f16x2 (lo = first arg), round-to-nearest
__device__ __forceinline__ uint32_t packh2(float lo, float hi) {
    uint32_t w;
    asm("cvt.rn.f16x2.f32 %0, %1, %2;" : "=r"(w) : "f"(hi), "f"(lo));
    return w;
}

// m16n8k16 with fp16 accumulators: C/D = 2 b32 regs (reg0 = row r cols 2c,2c+1;
// reg1 = row r+8), halving accumulator registers vs f32 C.
__device__ __forceinline__ void mma_f16c(uint32_t* c,
                                         uint32_t a0, uint32_t a1, uint32_t a2, uint32_t a3,
                                         uint32_t b0, uint32_t b1) {
    asm volatile("mma.sync.aligned.m16n8k16.row.col.f16.f16.f16.f16 "
                 "{%0,%1}, {%2,%3,%4,%5}, {%6,%7}, {%0,%1};"
                 : "+r"(c[0]), "+r"(c[1])
                 : "r"(a0), "r"(a1), "r"(a2), "r"(a3), "r"(b0), "r"(b1));
}

// GELU via tanh approximation + MUFU tanh (6 instrs)
__device__ __forceinline__ float gelu_fast(float x) {
    float t = x * x;
    float c = fmaf(t, 0.035677408136f, 0.7978845608028654f);
    float arg = x * c;
    float th;
    asm("tanh.approx.f32 %0, %1;" : "=f"(th) : "f"(arg));
    return x * fmaf(th, 0.5f, 0.5f);
}

// ---------------- W1 -> fp16 fragment-pair-order gmem (prep) ----------------
// Layout: [blk(64)][ks(2)][np(8)][lane(32)] uint4{b0_lo, b0_hi, b1_lo, b1_hi}
//   blk = ng*8 + kb ; k = kb*32 + ks*16 + (lane%4)*2 ; n = ng*128 + np*16 + lane/4
//   b0_lo = h2(W1[k][n],   W1[k+1][n])   b0_hi = h2(W1[k+8][n],   W1[k+9][n])
//   b1_lo = h2(W1[k][n+8], W1[k+1][n+8]) b1_hi = h2(W1[k+8][n+8], W1[k+9][n+8])
__device__ __align__(16) uint4 g_bfrag[32768];

__global__ void prep_bfrag_kernel(const float* __restrict__ W1) {
    int idx = blockIdx.x * blockDim.x + threadIdx.x;   // 0 .. 32767
    int lane = idx & 31;
    int np   = (idx >> 5) & 7;
    int ks   = (idx >> 8) & 1;
    int blk  = idx >> 9;                               // 0..63
    int ng = blk >> 3;
    int kb = blk & 7;
    int k = kb * 32 + ks * 16 + (lane & 3) * 2;
    int n = ng * 128 + np * 16 + (lane >> 2);
    uint4 v;
    v.x = packh2(W1[k * 1024 + n],           W1[(k + 1) * 1024 + n]);
    v.y = packh2(W1[(k + 8) * 1024 + n],     W1[(k + 9) * 1024 + n]);
    v.z = packh2(W1[k * 1024 + n + 8],       W1[(k + 1) * 1024 + n + 8]);
    v.w = packh2(W1[(k + 8) * 1024 + n + 8], W1[(k + 9) * 1024 + n + 8]);
    g_bfrag[idx] = v;
}

// ---------------- main fused kernel ----------------
__global__ void __launch_bounds__(NTHREADS, 2)
fused_mlp_kernel(const float* __restrict__ emb,
                 const int*   __restrict__ idxg,
                 const int*   __restrict__ idxd,
                 const float* __restrict__ b1,
                 const float* __restrict__ W2,
                 const float* __restrict__ b2,
                 float*       __restrict__ out) {
    extern __shared__ char smem[];
    const int tid   = threadIdx.x;
    const int wid   = tid >> 5;
    const int lane  = tid & 31;
    const int mwarp = wid & 3;        // 0..3 -> rows mwarp*32
    const int nwarp = wid >> 2;       // 0..1 -> cols nwarp*64 within group
    const int base  = blockIdx.x * TILE_M;

    // ---- stage idx / b1 / W2 ----
    if (tid < 128)      ((int*)(smem + OFF_IDX))[tid] = idxg[base + tid];
    else                ((int*)(smem + OFF_IDX))[tid] = idxd[base + tid - 128];
    for (int i = tid; i < 1024; i += NTHREADS)
        ((float*)(smem + OFF_B1))[i] = b1[i];
    for (int i = tid; i < 1024; i += NTHREADS)
        ((float2*)(smem + OFF_W2))[i] = ((const float2*)W2)[i];
    __syncthreads();

    // ---- gather A into fp16 fragment-order smem ----
    // [ks(16)][mt(8)][lane(32)] uint4 {a0,a1,a2,a3} (m16n8k16 A layout)
    {
        const int* idxs = (const int*)(smem + OFF_IDX);
        uint32_t* As32 = (uint32_t*)(smem + OFF_A);
        for (int i = tid; i < 8192; i += NTHREADS) {
            int m = i >> 6;
            int q = i & 63;
            int half_ = q >> 5;
            int c4    = q & 31;
            int node = idxs[half_ * 128 + m];
            float4 v = *(const float4*)(emb + (size_t)node * 128 + (size_t)c4 * 4);
            uint32_t w0 = packh2(v.x, v.y);    // cols (k, k+1)
            uint32_t w1 = packh2(v.z, v.w);    // cols (k+2, k+3)
            int kg  = half_ * 128 + c4 * 4;    // global K, multiple of 4
            int ks  = kg >> 4;                 // 0..15
            int kin = kg & 15;                 // 0,4,8,12
            int q0  = kin >> 1;                // pair index 0,2,4,6
            int clow = q0 & 3;                 // lane low bits for w0; w1 -> +1
            int slot = (((m & 15) >= 8) ? 1 : 0) + ((q0 >= 4) ? 2 : 0);
            int mt = m >> 4;
            int lane0 = (m & 7) * 4 + clow;
            uint32_t* dst = As32 + (((ks * 8 + mt) * 32 + lane0) << 2) + slot;
            dst[0] = w0;
            dst[4] = w1;                       // next lane, same slot
        }
    }

    // ---- preload B blocks 0 and 1 (two separate cp.async groups) ----
    const char* bsrc = (const char*)g_bfrag;
#pragma unroll
    for (int s = 0; s < 2; s++) {
        uint32_t dsts = smem_u32(smem + OFF_B + s * BBLK_BYTES);
        const char* srcs = bsrc + (size_t)s * BBLK_BYTES;
#pragma unroll
        for (int j = 0; j < 2; j++) {
            int L = tid + j * NTHREADS;                  // 0..511 x16B = 8KB
            CP_ASYNC16(dsts + L * 16, srcs + L * 16);
        }
        CP_COMMIT();
    }

    const float*  b1s = (const float*)(smem + OFF_B1);
    const float2* w2s = (const float2*)(smem + OFF_W2);
    float2 o[4];
    o[0] = make_float2(0.f, 0.f); o[1] = make_float2(0.f, 0.f);
    o[2] = make_float2(0.f, 0.f); o[3] = make_float2(0.f, 0.f);

    const uint4* Af = (const uint4*)(smem + OFF_A);
    int s_cur = 0;   // slot of current block (blk % 3)
    int s_pf  = 2;   // slot of block blk+2

    for (int ng = 0; ng < NGROUPS; ng++) {
        // fp16 accumulators: [mt][nt][reg] (reg0=row r, reg1=row r+8)
        uint32_t hacc[2][8][2];
#pragma unroll
        for (int mt = 0; mt < 2; mt++)
#pragma unroll
            for (int nt = 0; nt < 8; nt++) {
                hacc[mt][nt][0] = 0u;
                hacc[mt][nt][1] = 0u;
            }

        for (int kb = 0; kb < NKB; kb++) {
            int blk = ng * NKB + kb;
            // wait until block blk resident (in flight: blk, blk+1)
            if (blk + 1 < NBLOCKS) { CP_WAIT(1); } else { CP_WAIT(0); }
            __syncthreads();   // also fences reads of slot written by next prefetch
            // prefetch block blk+2 into slot (blk+2)%3 (read at iter blk-1, safe)
            if (blk + 2 < NBLOCKS) {
                uint32_t dstn = smem_u32(smem + OFF_B + s_pf * BBLK_BYTES);
                const char* srcn = bsrc + (size_t)(blk + 2) * BBLK_BYTES;
#pragma unroll
                for (int j = 0; j < 2; j++) {
                    int L = tid + j * NTHREADS;
                    CP_ASYNC16(dstn + L * 16, srcn + L * 16);
                }
                CP_COMMIT();
            }

            const uint4* Bf = (const uint4*)(smem + OFF_B + s_cur * BBLK_BYTES);
#pragma unroll
            for (int ks = 0; ks < 2; ks++) {
                int ksg = kb * 2 + ks;       // 0..15
                uint4 a0 = Af[(ksg * 8 + mwarp * 2 + 0) * 32 + lane];
                uint4 a1 = Af[(ksg * 8 + mwarp * 2 + 1) * 32 + lane];
#pragma unroll
                for (int p = 0; p < 4; p++) {
                    uint4 b = Bf[(ks * 8 + nwarp * 4 + p) * 32 + lane];
                    mma_f16c(hacc[0][2 * p + 0], a0.x, a0.y, a0.z, a0.w, b.x, b.y);
                    mma_f16c(hacc[0][2 * p + 1], a0.x, a0.y, a0.z, a0.w, b.z, b.w);
                    mma_f16c(hacc[1][2 * p + 0], a1.x, a1.y, a1.z, a1.w, b.x, b.y);
                    mma_f16c(hacc[1][2 * p + 1], a1.x, a1.y, a1.z, a1.w, b.z, b.w);
                }
            }
            // advance ring
            s_cur = (s_cur == 2) ? 0 : s_cur + 1;
            s_pf  = (s_pf  == 2) ? 0 : s_pf  + 1;
        }

        // ---- fused epilogue: unpack fp16 h, +b1 (f32), GELU, x W2 (f32) ----
        int jb = ng * 128 + nwarp * 64 + (lane & 3) * 2;
#pragma unroll
        for (int nt = 0; nt < 8; nt++) {
            int j = jb + nt * 8;
            float  bb0 = b1s[j],     bb1 = b1s[j + 1];
            float2 w0  = w2s[j];
            float2 w1  = w2s[j + 1];
#pragma unroll
            for (int mt = 0; mt < 2; mt++) {
#pragma unroll
                for (int sh = 0; sh < 2; sh++) {
                    int oi = mt * 2 + sh;
                    __half2 hp = *reinterpret_cast<__half2*>(&hacc[mt][nt][sh]);
                    float2 hf = __half22float2(hp);
                    float g0 = gelu_fast(hf.x + bb0);
                    float g1 = gelu_fast(hf.y + bb1);
                    o[oi].x = fmaf(g0, w0.x, o[oi].x);
                    o[oi].y = fmaf(g0, w0.y, o[oi].y);
                    o[oi].x = fmaf(g1, w1.x, o[oi].x);
                    o[oi].y = fmaf(g1, w1.y, o[oi].y);
                }
            }
        }
    }

    // ---- reduce within quads (lanes sharing a row) ----
#pragma unroll
    for (int oi = 0; oi < 4; oi++) {
        o[oi].x += __shfl_xor_sync(0xFFFFFFFFu, o[oi].x, 1);
        o[oi].x += __shfl_xor_sync(0xFFFFFFFFu, o[oi].x, 2);
        o[oi].y += __shfl_xor_sync(0xFFFFFFFFu, o[oi].y, 1);
        o[oi].y += __shfl_xor_sync(0xFFFFFFFFu, o[oi].y, 2);
    }

    // ---- combine the two n-warps, add b2, write out ----
    float2* cmb = (float2*)(smem + OFF_CMB);
    int g = lane >> 2;
    __syncthreads();
    if (nwarp == 1 && (lane & 3) == 0) {
#pragma unroll
        for (int oi = 0; oi < 4; oi++) {
            int r = mwarp * 32 + (oi >> 1) * 16 + (oi & 1) * 8 + g;
            cmb[r] = o[oi];
        }
    }
    __syncthreads();
    if (nwarp == 0 && (lane & 3) == 0) {
        float b20 = __ldg(&b2[0]);
        float b21 = __ldg(&b2[1]);
#pragma unroll
        for (int oi = 0; oi < 4; oi++) {
            int r = mwarp * 32 + (oi >> 1) * 16 + (oi & 1) * 8 + g;
            float2 c = cmb[r];
            float2 res;
            res.x = o[oi].x + c.x + b20;
            res.y = o[oi].y + c.y + b21;
            ((float2*)out)[base + r] = res;
        }
    }
}

// ---------------- launch ----------------
extern "C" void kernel_launch(void* const* d_in, const int* in_sizes, int n_in,
                              void* d_out, int out_size) {
    const float* emb  = (const float*)d_in[0];
    const int*   idxg = (const int*)d_in[1];
    const int*   idxd = (const int*)d_in[2];
    const float* W1   = (const float*)d_in[3];
    const float* b1   = (const float*)d_in[4];
    const float* W2   = (const float*)d_in[5];
    const float* b2   = (const float*)d_in[6];
    float* out = (float*)d_out;

    static bool configured = false;
    if (!configured) {
        cudaFuncSetAttribute(fused_mlp_kernel,
                             cudaFuncAttributeMaxDynamicSharedMemorySize, SMEM_BYTES);
        configured = true;
    }

    prep_bfrag_kernel<<<128, 256>>>(W1);
    fused_mlp_kernel<<<2048, NTHREADS, SMEM_BYTES>>>(emb, idxg, idxd, b1, W2, b2, out);
}

// round 15
// speedup vs baseline: 1.1214x; 1.1214x over previous
// Fused gather+concat -> Linear(256,1024) -> GELU -> Linear(1024,2)
// sm_100 legacy mma.sync fp16 m16n8k16 with fp16 C-fragments, 2 CTAs/SM.
// R15: warp tile 64x64 (2 mwarps x 4 nwarps), 64 fp16-C accumulator regs.
// B fragment re-reads halve (each B read by 2 mwarps, not 4): LDS 3.5->2.5MB/CTA.
// N-groups of 256 cols (NGROUPS=4); B blocks [32K x 256c] = 16KB, 2-slot
// double buffer (R9-verified pattern). Numerics bit-identical to R14.

#include <cuda_runtime.h>
#include <cuda_fp16.h>
#include <cstdint>

#define NTHREADS   256
#define TILE_M     128
#define NGROUPS    4           // 1024 / 256
#define NKB        8           // K blocks per group-sweep: 8 x 32 = 256
#define NBLOCKS    32          // ngroups * nkb, linear B stream
#define BBLK_BYTES 16384       // 32 K x 256 cols x 2B

// smem layout (bytes)
#define OFF_IDX    0           // 256 ints
#define OFF_B1     2048        // 1024 f32
#define OFF_W2     6144        // 1024 float2
#define OFF_A      14336       // A frags: 16 ksteps x 8 mtiles x 32 lanes x 16B = 65536
#define OFF_B      79872       // 2 x 16KB B buffers (reused as combine buf at end)
#define SMEM_BYTES 112640

// ---------------- helpers ----------------
__device__ __forceinline__ uint32_t smem_u32(const void* p) {
    uint32_t a;
    asm("{ .reg .u64 t; cvta.to.shared.u64 t, %1; cvt.u32.u64 %0, t; }"
        : "=r"(a) : "l"(p));
    return a;
}

#define CP_ASYNC16(dst, src) \
    asm volatile("cp.async.cg.shared.global [%0], [%1], 16;" :: "r"(dst), "l"(src))
#define CP_COMMIT() asm volatile("cp.async.commit_group;" ::: "memory")
#define CP_WAIT(n)  asm volatile("cp.async.wait_group %0;" :: "n"(n) : "memory")

// pack two f32 -> f16x2 (lo = first arg), round-to-nearest
__device__ __forceinline__ uint32_t packh2(float lo, float hi) {
    uint32_t w;
    asm("cvt.rn.f16x2.f32 %0, %1, %2;" : "=r"(w) : "f"(hi), "f"(lo));
    return w;
}

// m16n8k16 with fp16 accumulators: C/D = 2 b32 regs (reg0 = row r cols 2c,2c+1;
// reg1 = row r+8).
__device__ __forceinline__ void mma_f16c(uint32_t* c,
                                         uint32_t a0, uint32_t a1, uint32_t a2, uint32_t a3,
                                         uint32_t b0, uint32_t b1) {
    asm volatile("mma.sync.aligned.m16n8k16.row.col.f16.f16.f16.f16 "
                 "{%0,%1}, {%2,%3,%4,%5}, {%6,%7}, {%0,%1};"
                 : "+r"(c[0]), "+r"(c[1])
                 : "r"(a0), "r"(a1), "r"(a2), "r"(a3), "r"(b0), "r"(b1));
}

// GELU via tanh approximation + MUFU tanh (6 instrs)
__device__ __forceinline__ float gelu_fast(float x) {
    float t = x * x;
    float c = fmaf(t, 0.035677408136f, 0.7978845608028654f);
    float arg = x * c;
    float th;
    asm("tanh.approx.f32 %0, %1;" : "=f"(th) : "f"(arg));
    return x * fmaf(th, 0.5f, 0.5f);
}

// ---------------- W1 -> fp16 fragment-pair-order gmem (prep) ----------------
// Layout: [blk(32)][ks(2)][np(16)][lane(32)] uint4{b0_lo, b0_hi, b1_lo, b1_hi}
//   blk = ng*8 + kb ; k = kb*32 + ks*16 + (lane%4)*2 ; n = ng*256 + np*16 + lane/4
//   b0_lo = h2(W1[k][n],   W1[k+1][n])   b0_hi = h2(W1[k+8][n],   W1[k+9][n])
//   b1_lo = h2(W1[k][n+8], W1[k+1][n+8]) b1_hi = h2(W1[k+8][n+8], W1[k+9][n+8])
__device__ __align__(16) uint4 g_bfrag[32768];

__global__ void prep_bfrag_kernel(const float* __restrict__ W1) {
    int idx = blockIdx.x * blockDim.x + threadIdx.x;   // 0 .. 32767
    int lane = idx & 31;
    int np   = (idx >> 5) & 15;
    int ks   = (idx >> 9) & 1;
    int blk  = idx >> 10;                              // 0..31
    int ng = blk >> 3;
    int kb = blk & 7;
    int k = kb * 32 + ks * 16 + (lane & 3) * 2;
    int n = ng * 256 + np * 16 + (lane >> 2);
    uint4 v;
    v.x = packh2(W1[k * 1024 + n],           W1[(k + 1) * 1024 + n]);
    v.y = packh2(W1[(k + 8) * 1024 + n],     W1[(k + 9) * 1024 + n]);
    v.z = packh2(W1[k * 1024 + n + 8],       W1[(k + 1) * 1024 + n + 8]);
    v.w = packh2(W1[(k + 8) * 1024 + n + 8], W1[(k + 9) * 1024 + n + 8]);
    g_bfrag[idx] = v;
}

// ---------------- main fused kernel ----------------
__global__ void __launch_bounds__(NTHREADS, 2)
fused_mlp_kernel(const float* __restrict__ emb,
                 const int*   __restrict__ idxg,
                 const int*   __restrict__ idxd,
                 const float* __restrict__ b1,
                 const float* __restrict__ W2,
                 const float* __restrict__ b2,
                 float*       __restrict__ out) {
    extern __shared__ char smem[];
    const int tid   = threadIdx.x;
    const int wid   = tid >> 5;
    const int lane  = tid & 31;
    const int mwarp = wid & 1;        // 0..1 -> rows mwarp*64
    const int nwarp = wid >> 1;       // 0..3 -> cols nwarp*64 within group
    const int base  = blockIdx.x * TILE_M;

    // ---- stage idx / b1 / W2 ----
    if (tid < 128)      ((int*)(smem + OFF_IDX))[tid] = idxg[base + tid];
    else                ((int*)(smem + OFF_IDX))[tid] = idxd[base + tid - 128];
    for (int i = tid; i < 1024; i += NTHREADS)
        ((float*)(smem + OFF_B1))[i] = b1[i];
    for (int i = tid; i < 1024; i += NTHREADS)
        ((float2*)(smem + OFF_W2))[i] = ((const float2*)W2)[i];
    __syncthreads();

    // ---- gather A into fp16 fragment-order smem ----
    // [ks(16)][mt(8)][lane(32)] uint4 {a0,a1,a2,a3} (m16n8k16 A layout)
    {
        const int* idxs = (const int*)(smem + OFF_IDX);
        uint32_t* As32 = (uint32_t*)(smem + OFF_A);
        for (int i = tid; i < 8192; i += NTHREADS) {
            int m = i >> 6;
            int q = i & 63;
            int half_ = q >> 5;
            int c4    = q & 31;
            int node = idxs[half_ * 128 + m];
            float4 v = *(const float4*)(emb + (size_t)node * 128 + (size_t)c4 * 4);
            uint32_t w0 = packh2(v.x, v.y);    // cols (k, k+1)
            uint32_t w1 = packh2(v.z, v.w);    // cols (k+2, k+3)
            int kg  = half_ * 128 + c4 * 4;    // global K, multiple of 4
            int ks  = kg >> 4;                 // 0..15
            int kin = kg & 15;                 // 0,4,8,12
            int q0  = kin >> 1;                // pair index 0,2,4,6
            int clow = q0 & 3;                 // lane low bits for w0; w1 -> +1
            int slot = (((m & 15) >= 8) ? 1 : 0) + ((q0 >= 4) ? 2 : 0);
            int mt = m >> 4;
            int lane0 = (m & 7) * 4 + clow;
            uint32_t* dst = As32 + (((ks * 8 + mt) * 32 + lane0) << 2) + slot;
            dst[0] = w0;
            dst[4] = w1;                       // next lane, same slot
        }
    }

    // ---- preload B block 0 ----
    const char* bsrc = (const char*)g_bfrag;
    {
        uint32_t dst0 = smem_u32(smem + OFF_B);
#pragma unroll
        for (int j = 0; j < 4; j++) {
            int L = tid + j * NTHREADS;                  // 0..1023 x16B = 16KB
            CP_ASYNC16(dst0 + L * 16, bsrc + L * 16);
        }
        CP_COMMIT();
    }

    const float*  b1s = (const float*)(smem + OFF_B1);
    const float2* w2s = (const float2*)(smem + OFF_W2);
    float2 o[8];
#pragma unroll
    for (int oi = 0; oi < 8; oi++) o[oi] = make_float2(0.f, 0.f);

    const uint4* Af = (const uint4*)(smem + OFF_A);

    for (int ng = 0; ng < NGROUPS; ng++) {
        // fp16 accumulators: [mt(4)][nt(8)][reg(2)] (reg0=row r, reg1=row r+8)
        uint32_t hacc[4][8][2];
#pragma unroll
        for (int mt = 0; mt < 4; mt++)
#pragma unroll
            for (int nt = 0; nt < 8; nt++) {
                hacc[mt][nt][0] = 0u;
                hacc[mt][nt][1] = 0u;
            }

        for (int kb = 0; kb < NKB; kb++) {
            int blk = ng * NKB + kb;
            // prefetch next block into the other slot (it was last read at
            // iter blk-1 and fenced by that iter's trailing barrier)
            if (blk + 1 < NBLOCKS) {
                uint32_t dstn = smem_u32(smem + OFF_B + ((blk + 1) & 1) * BBLK_BYTES);
                const char* srcn = bsrc + (size_t)(blk + 1) * BBLK_BYTES;
#pragma unroll
                for (int j = 0; j < 4; j++) {
                    int L = tid + j * NTHREADS;
                    CP_ASYNC16(dstn + L * 16, srcn + L * 16);
                }
                CP_COMMIT();
                CP_WAIT(1);
            } else {
                CP_WAIT(0);
            }
            __syncthreads();   // block blk visible to all warps

            const uint4* Bf = (const uint4*)(smem + OFF_B + (blk & 1) * BBLK_BYTES);
#pragma unroll
            for (int ks = 0; ks < 2; ks++) {
                int ksg = kb * 2 + ks;       // 0..15
                uint4 a0 = Af[(ksg * 8 + mwarp * 4 + 0) * 32 + lane];
                uint4 a1 = Af[(ksg * 8 + mwarp * 4 + 1) * 32 + lane];
                uint4 a2 = Af[(ksg * 8 + mwarp * 4 + 2) * 32 + lane];
                uint4 a3 = Af[(ksg * 8 + mwarp * 4 + 3) * 32 + lane];
#pragma unroll
                for (int p = 0; p < 4; p++) {
                    uint4 b = Bf[(ks * 16 + nwarp * 4 + p) * 32 + lane];
                    mma_f16c(hacc[0][2 * p + 0], a0.x, a0.y, a0.z, a0.w, b.x, b.y);
                    mma_f16c(hacc[0][2 * p + 1], a0.x, a0.y, a0.z, a0.w, b.z, b.w);
                    mma_f16c(hacc[1][2 * p + 0], a1.x, a1.y, a1.z, a1.w, b.x, b.y);
                    mma_f16c(hacc[1][2 * p + 1], a1.x, a1.y, a1.z, a1.w, b.z, b.w);
                    mma_f16c(hacc[2][2 * p + 0], a2.x, a2.y, a2.z, a2.w, b.x, b.y);
                    mma_f16c(hacc[2][2 * p + 1], a2.x, a2.y, a2.z, a2.w, b.z, b.w);
                    mma_f16c(hacc[3][2 * p + 0], a3.x, a3.y, a3.z, a3.w, b.x, b.y);
                    mma_f16c(hacc[3][2 * p + 1], a3.x, a3.y, a3.z, a3.w, b.z, b.w);
                }
            }
            __syncthreads();   // all warps done reading blk before blk+2 lands
        }

        // ---- fused epilogue: unpack fp16 h, +b1 (f32), GELU, x W2 (f32) ----
        int jb = ng * 256 + nwarp * 64 + (lane & 3) * 2;
#pragma unroll
        for (int nt = 0; nt < 8; nt++) {
            int j = jb + nt * 8;
            float  bb0 = b1s[j],     bb1 = b1s[j + 1];
            float2 w0  = w2s[j];
            float2 w1  = w2s[j + 1];
#pragma unroll
            for (int mt = 0; mt < 4; mt++) {
#pragma unroll
                for (int sh = 0; sh < 2; sh++) {
                    int oi = mt * 2 + sh;
                    __half2 hp = *reinterpret_cast<__half2*>(&hacc[mt][nt][sh]);
                    float2 hf = __half22float2(hp);
                    float g0 = gelu_fast(hf.x + bb0);
                    float g1 = gelu_fast(hf.y + bb1);
                    o[oi].x = fmaf(g0, w0.x, o[oi].x);
                    o[oi].y = fmaf(g0, w0.y, o[oi].y);
                    o[oi].x = fmaf(g1, w1.x, o[oi].x);
                    o[oi].y = fmaf(g1, w1.y, o[oi].y);
                }
            }
        }
    }

    // ---- reduce within quads (lanes sharing a row) ----
#pragma unroll
    for (int oi = 0; oi < 8; oi++) {
        o[oi].x += __shfl_xor_sync(0xFFFFFFFFu, o[oi].x, 1);
        o[oi].x += __shfl_xor_sync(0xFFFFFFFFu, o[oi].x, 2);
        o[oi].y += __shfl_xor_sync(0xFFFFFFFFu, o[oi].y, 1);
        o[oi].y += __shfl_xor_sync(0xFFFFFFFFu, o[oi].y, 2);
    }

    // ---- combine the four n-warps (B ring area reused as scratch) ----
    float2* cmb = (float2*)(smem + OFF_B);   // [3][128] float2
    int g = lane >> 2;
    __syncthreads();                          // mainloop reads done; safe reuse
    if (nwarp > 0 && (lane & 3) == 0) {
#pragma unroll
        for (int oi = 0; oi < 8; oi++) {
            int r = mwarp * 64 + (oi >> 1) * 16 + (oi & 1) * 8 + g;
            cmb[(nwarp - 1) * 128 + r] = o[oi];
        }
    }
    __syncthreads();
    if (nwarp == 0 && (lane & 3) == 0) {
        float b20 = __ldg(&b2[0]);
        float b21 = __ldg(&b2[1]);
#pragma unroll
        for (int oi = 0; oi < 8; oi++) {
            int r = mwarp * 64 + (oi >> 1) * 16 + (oi & 1) * 8 + g;
            float2 c0 = cmb[r];
            float2 c1 = cmb[128 + r];
            float2 c2 = cmb[256 + r];
            float2 res;
            res.x = o[oi].x + c0.x + c1.x + c2.x + b20;
            res.y = o[oi].y + c0.y + c1.y + c2.y + b21;
            ((float2*)out)[base + r] = res;
        }
    }
}

// ---------------- launch ----------------
extern "C" void kernel_launch(void* const* d_in, const int* in_sizes, int n_in,
                              void* d_out, int out_size) {
    const float* emb  = (const float*)d_in[0];
    const int*   idxg = (const int*)d_in[1];
    const int*   idxd = (const int*)d_in[2];
    const float* W1   = (const float*)d_in[3];
    const float* b1   = (const float*)d_in[4];
    const float* W2   = (const float*)d_in[5];
    const float* b2   = (const float*)d_in[6];
    float* out = (float*)d_out;

    static bool configured = false;
    if (!configured) {
        cudaFuncSetAttribute(fused_mlp_kernel,
                             cudaFuncAttributeMaxDynamicSharedMemorySize, SMEM_BYTES);
        configured = true;
    }

    prep_bfrag_kernel<<<128, 256>>>(W1);
    fused_mlp_kernel<<<2048, NTHREADS, SMEM_BYTES>>>(emb, idxg, idxd, b1, W2, b2, out);
}

// round 17
// speedup vs baseline: 1.2427x; 1.1082x over previous
// Fused gather+concat -> Linear(256,1024) -> GELU -> Linear(1024,2)
// sm_100 legacy mma.sync fp16 m16n8k16, fp16 C-fragments, 2 CTAs/SM.
// R16 resubmit (bench driver Trio exception = infra flake; R5/R7/R10/R12
// precedent: identical source passed on retry).
// Per-warp self-paced B streaming. Each warp cp.asyncs its own private
// [K=16 x 64col] 2KB B slices (2-slot ring, warp-private), synced only by
// cp.async.wait_group + __syncwarp -> ZERO __syncthreads in the mainloop.
// Warp tile 64x64 (2 mwarps x 4 nwarps), 64 fp16-C accumulators.
// Cost: B slices duplicated across the 2 mwarps (extra 0.5MB STS, +1MB L2).

#include <cuda_runtime.h>
#include <cuda_fp16.h>
#include <cstdint>

#define NTHREADS   256
#define TILE_M     128
#define NGROUPS    4           // 1024 / 256
#define NKB        16          // K blocks per group-sweep: 16 x 16 = 256
#define NBLOCKS    64          // ngroups * nkb, linear per-warp B stream
#define WSLICE     2048        // per-warp B slice: 16K x 64 cols x 2B

// smem layout (bytes)
#define OFF_IDX    0           // 256 ints
#define OFF_B1     2048        // 1024 f32
#define OFF_W2     6144        // 1024 float2
#define OFF_A      14336       // A frags: 16 ksteps x 8 mtiles x 32 lanes x 16B = 65536
#define OFF_B      79872       // 8 warps x 2 slots x 2KB = 32KB (reused as combine buf)
#define SMEM_BYTES 112640

// ---------------- helpers ----------------
__device__ __forceinline__ uint32_t smem_u32(const void* p) {
    uint32_t a;
    asm("{ .reg .u64 t; cvta.to.shared.u64 t, %1; cvt.u32.u64 %0, t; }"
        : "=r"(a) : "l"(p));
    return a;
}

#define CP_ASYNC16(dst, src) \
    asm volatile("cp.async.cg.shared.global [%0], [%1], 16;" :: "r"(dst), "l"(src))
#define CP_COMMIT() asm volatile("cp.async.commit_group;" ::: "memory")
#define CP_WAIT(n)  asm volatile("cp.async.wait_group %0;" :: "n"(n) : "memory")

// pack two f32 -> f16x2 (lo = first arg), round-to-nearest
__device__ __forceinline__ uint32_t packh2(float lo, float hi) {
    uint32_t w;
    asm("cvt.rn.f16x2.f32 %0, %1, %2;" : "=r"(w) : "f"(hi), "f"(lo));
    return w;
}

// m16n8k16 with fp16 accumulators: C/D = 2 b32 regs (reg0 = row r cols 2c,2c+1;
// reg1 = row r+8).
__device__ __forceinline__ void mma_f16c(uint32_t* c,
                                         uint32_t a0, uint32_t a1, uint32_t a2, uint32_t a3,
                                         uint32_t b0, uint32_t b1) {
    asm volatile("mma.sync.aligned.m16n8k16.row.col.f16.f16.f16.f16 "
                 "{%0,%1}, {%2,%3,%4,%5}, {%6,%7}, {%0,%1};"
                 : "+r"(c[0]), "+r"(c[1])
                 : "r"(a0), "r"(a1), "r"(a2), "r"(a3), "r"(b0), "r"(b1));
}

// GELU via tanh approximation + MUFU tanh (6 instrs)
__device__ __forceinline__ float gelu_fast(float x) {
    float t = x * x;
    float c = fmaf(t, 0.035677408136f, 0.7978845608028654f);
    float arg = x * c;
    float th;
    asm("tanh.approx.f32 %0, %1;" : "=f"(th) : "f"(arg));
    return x * fmaf(th, 0.5f, 0.5f);
}

// ---------------- W1 -> per-warp-slice fragment order gmem (prep) ----------------
// Layout: [ng(4)][kb(16)][nwarp(4)][np(4)][lane(32)] uint4{b0_lo,b0_hi,b1_lo,b1_hi}
//   k = kb*16 + (lane%4)*2 ; n = ng*256 + nwarp*64 + np*16 + lane/4
//   b0_lo = h2(W1[k][n],   W1[k+1][n])   b0_hi = h2(W1[k+8][n],   W1[k+9][n])
//   b1_lo = h2(W1[k][n+8], W1[k+1][n+8]) b1_hi = h2(W1[k+8][n+8], W1[k+9][n+8])
__device__ __align__(16) uint4 g_bfrag[32768];

__global__ void prep_bfrag_kernel(const float* __restrict__ W1) {
    int idx = blockIdx.x * blockDim.x + threadIdx.x;   // 0 .. 32767
    int lane  = idx & 31;
    int np    = (idx >> 5) & 3;
    int nwarp = (idx >> 7) & 3;
    int kb    = (idx >> 9) & 15;
    int ng    = idx >> 13;
    int k = kb * 16 + (lane & 3) * 2;
    int n = ng * 256 + nwarp * 64 + np * 16 + (lane >> 2);
    uint4 v;
    v.x = packh2(W1[k * 1024 + n],           W1[(k + 1) * 1024 + n]);
    v.y = packh2(W1[(k + 8) * 1024 + n],     W1[(k + 9) * 1024 + n]);
    v.z = packh2(W1[k * 1024 + n + 8],       W1[(k + 1) * 1024 + n + 8]);
    v.w = packh2(W1[(k + 8) * 1024 + n + 8], W1[(k + 9) * 1024 + n + 8]);
    g_bfrag[idx] = v;
}

// ---------------- main fused kernel ----------------
__global__ void __launch_bounds__(NTHREADS, 2)
fused_mlp_kernel(const float* __restrict__ emb,
                 const int*   __restrict__ idxg,
                 const int*   __restrict__ idxd,
                 const float* __restrict__ b1,
                 const float* __restrict__ W2,
                 const float* __restrict__ b2,
                 float*       __restrict__ out) {
    extern __shared__ char smem[];
    const int tid   = threadIdx.x;
    const int wid   = tid >> 5;
    const int lane  = tid & 31;
    const int mwarp = wid & 1;        // 0..1 -> rows mwarp*64
    const int nwarp = wid >> 1;       // 0..3 -> cols nwarp*64 within group
    const int base  = blockIdx.x * TILE_M;

    // ---- stage idx / b1 / W2 ----
    if (tid < 128)      ((int*)(smem + OFF_IDX))[tid] = idxg[base + tid];
    else                ((int*)(smem + OFF_IDX))[tid] = idxd[base + tid - 128];
    for (int i = tid; i < 1024; i += NTHREADS)
        ((float*)(smem + OFF_B1))[i] = b1[i];
    for (int i = tid; i < 1024; i += NTHREADS)
        ((float2*)(smem + OFF_W2))[i] = ((const float2*)W2)[i];
    __syncthreads();

    // ---- gather A into fp16 fragment-order smem ----
    // [ks(16)][mt(8)][lane(32)] uint4 {a0,a1,a2,a3} (m16n8k16 A layout)
    {
        const int* idxs = (const int*)(smem + OFF_IDX);
        uint32_t* As32 = (uint32_t*)(smem + OFF_A);
        for (int i = tid; i < 8192; i += NTHREADS) {
            int m = i >> 6;
            int q = i & 63;
            int half_ = q >> 5;
            int c4    = q & 31;
            int node = idxs[half_ * 128 + m];
            float4 v = *(const float4*)(emb + (size_t)node * 128 + (size_t)c4 * 4);
            uint32_t w0 = packh2(v.x, v.y);    // cols (k, k+1)
            uint32_t w1 = packh2(v.z, v.w);    // cols (k+2, k+3)
            int kg  = half_ * 128 + c4 * 4;    // global K, multiple of 4
            int ks  = kg >> 4;                 // 0..15
            int kin = kg & 15;                 // 0,4,8,12
            int q0  = kin >> 1;                // pair index 0,2,4,6
            int clow = q0 & 3;                 // lane low bits for w0; w1 -> +1
            int slot = (((m & 15) >= 8) ? 1 : 0) + ((q0 >= 4) ? 2 : 0);
            int mt = m >> 4;
            int lane0 = (m & 7) * 4 + clow;
            uint32_t* dst = As32 + (((ks * 8 + mt) * 32 + lane0) << 2) + slot;
            dst[0] = w0;
            dst[4] = w1;                       // next lane, same slot
        }
    }
    __syncthreads();          // A (and b1/W2) visible to all warps; last CTA barrier
                              // until the output combine.

    // ---- per-warp B stream setup ----
    const char* bsrc = (const char*)g_bfrag;
    const uint32_t wslot = smem_u32(smem) + OFF_B + wid * (2 * WSLICE);
    // per-warp source offset for block blk: (blk*4 + nwarp) * WSLICE
    // preload blocks 0 and 1 into slots 0 and 1
#pragma unroll
    for (int s = 0; s < 2; s++) {
        const char* src = bsrc + (size_t)(s * 4 + nwarp) * WSLICE;
#pragma unroll
        for (int j = 0; j < 4; j++)
            CP_ASYNC16(wslot + s * WSLICE + j * 512 + lane * 16,
                       src + j * 512 + lane * 16);
        CP_COMMIT();
    }

    const float*  b1s = (const float*)(smem + OFF_B1);
    const float2* w2s = (const float2*)(smem + OFF_W2);
    float2 o[8];
#pragma unroll
    for (int oi = 0; oi < 8; oi++) o[oi] = make_float2(0.f, 0.f);

    const uint4* Af = (const uint4*)(smem + OFF_A);

    for (int ng = 0; ng < NGROUPS; ng++) {
        // fp16 accumulators: [mt(4)][nt(8)][reg(2)] (reg0=row r, reg1=row r+8)
        uint32_t hacc[4][8][2];
#pragma unroll
        for (int mt = 0; mt < 4; mt++)
#pragma unroll
            for (int nt = 0; nt < 8; nt++) {
                hacc[mt][nt][0] = 0u;
                hacc[mt][nt][1] = 0u;
            }

        for (int kb = 0; kb < NKB; kb++) {
            int blk = ng * NKB + kb;
            // wait for block blk (own groups; blk+1 may stay in flight)
            if (blk + 1 < NBLOCKS) { CP_WAIT(1); } else { CP_WAIT(0); }
            __syncwarp();

            const uint4* Bf = (const uint4*)(smem + OFF_B + wid * (2 * WSLICE)
                                             + (blk & 1) * WSLICE);
            uint4 a0 = Af[(kb * 8 + mwarp * 4 + 0) * 32 + lane];
            uint4 a1 = Af[(kb * 8 + mwarp * 4 + 1) * 32 + lane];
            uint4 a2 = Af[(kb * 8 + mwarp * 4 + 2) * 32 + lane];
            uint4 a3 = Af[(kb * 8 + mwarp * 4 + 3) * 32 + lane];
#pragma unroll
            for (int p = 0; p < 4; p++) {
                uint4 b = Bf[p * 32 + lane];
                mma_f16c(hacc[0][2 * p + 0], a0.x, a0.y, a0.z, a0.w, b.x, b.y);
                mma_f16c(hacc[0][2 * p + 1], a0.x, a0.y, a0.z, a0.w, b.z, b.w);
                mma_f16c(hacc[1][2 * p + 0], a1.x, a1.y, a1.z, a1.w, b.x, b.y);
                mma_f16c(hacc[1][2 * p + 1], a1.x, a1.y, a1.z, a1.w, b.z, b.w);
                mma_f16c(hacc[2][2 * p + 0], a2.x, a2.y, a2.z, a2.w, b.x, b.y);
                mma_f16c(hacc[2][2 * p + 1], a2.x, a2.y, a2.z, a2.w, b.z, b.w);
                mma_f16c(hacc[3][2 * p + 0], a3.x, a3.y, a3.z, a3.w, b.x, b.y);
                mma_f16c(hacc[3][2 * p + 1], a3.x, a3.y, a3.z, a3.w, b.z, b.w);
            }

            // prefetch block blk+2 into slot (blk&1): its 4 LDS above have
            // issued; cp.async writes land >= an L2 round-trip later.
            if (blk + 2 < NBLOCKS) {
                const char* src = bsrc + (size_t)((blk + 2) * 4 + nwarp) * WSLICE;
#pragma unroll
                for (int j = 0; j < 4; j++)
                    CP_ASYNC16(wslot + (blk & 1) * WSLICE + j * 512 + lane * 16,
                               src + j * 512 + lane * 16);
                CP_COMMIT();
            }
        }

        // ---- fused epilogue: unpack fp16 h, +b1 (f32), GELU, x W2 (f32) ----
        int jb = ng * 256 + nwarp * 64 + (lane & 3) * 2;
#pragma unroll
        for (int nt = 0; nt < 8; nt++) {
            int j = jb + nt * 8;
            float  bb0 = b1s[j],     bb1 = b1s[j + 1];
            float2 w0  = w2s[j];
            float2 w1  = w2s[j + 1];
#pragma unroll
            for (int mt = 0; mt < 4; mt++) {
#pragma unroll
                for (int sh = 0; sh < 2; sh++) {
                    int oi = mt * 2 + sh;
                    __half2 hp = *reinterpret_cast<__half2*>(&hacc[mt][nt][sh]);
                    float2 hf = __half22float2(hp);
                    float g0 = gelu_fast(hf.x + bb0);
                    float g1 = gelu_fast(hf.y + bb1);
                    o[oi].x = fmaf(g0, w0.x, o[oi].x);
                    o[oi].y = fmaf(g0, w0.y, o[oi].y);
                    o[oi].x = fmaf(g1, w1.x, o[oi].x);
                    o[oi].y = fmaf(g1, w1.y, o[oi].y);
                }
            }
        }
    }

    // ---- reduce within quads (lanes sharing a row) ----
#pragma unroll
    for (int oi = 0; oi < 8; oi++) {
        o[oi].x += __shfl_xor_sync(0xFFFFFFFFu, o[oi].x, 1);
        o[oi].x += __shfl_xor_sync(0xFFFFFFFFu, o[oi].x, 2);
        o[oi].y += __shfl_xor_sync(0xFFFFFFFFu, o[oi].y, 1);
        o[oi].y += __shfl_xor_sync(0xFFFFFFFFu, o[oi].y, 2);
    }

    // ---- combine the four n-warps (B area reused as scratch) ----
    float2* cmb = (float2*)(smem + OFF_B);   // [3][128] float2
    int g = lane >> 2;
    __syncthreads();                          // all warps past mainloop; B area free
    if (nwarp > 0 && (lane & 3) == 0) {
#pragma unroll
        for (int oi = 0; oi < 8; oi++) {
            int r = mwarp * 64 + (oi >> 1) * 16 + (oi & 1) * 8 + g;
            cmb[(nwarp - 1) * 128 + r] = o[oi];
        }
    }
    __syncthreads();
    if (nwarp == 0 && (lane & 3) == 0) {
        float b20 = __ldg(&b2[0]);
        float b21 = __ldg(&b2[1]);
#pragma unroll
        for (int oi = 0; oi < 8; oi++) {
            int r = mwarp * 64 + (oi >> 1) * 16 + (oi & 1) * 8 + g;
            float2 c0 = cmb[r];
            float2 c1 = cmb[128 + r];
            float2 c2 = cmb[256 + r];
            float2 res;
            res.x = o[oi].x + c0.x + c1.x + c2.x + b20;
            res.y = o[oi].y + c0.y + c1.y + c2.y + b21;
            ((float2*)out)[base + r] = res;
        }
    }
}

// ---------------- launch ----------------
extern "C" void kernel_launch(void* const* d_in, const int* in_sizes, int n_in,
                              void* d_out, int out_size) {
    const float* emb  = (const float*)d_in[0];
    const int*   idxg = (const int*)d_in[1];
    const int*   idxd = (const int*)d_in[2];
    const float* W1   = (const float*)d_in[3];
    const float* b1   = (const float*)d_in[4];
    const float* W2   = (const float*)d_in[5];
    const float* b2   = (const float*)d_in[6];
    float* out = (float*)d_out;

    static bool configured = false;
    if (!configured) {
        cudaFuncSetAttribute(fused_mlp_kernel,
                             cudaFuncAttributeMaxDynamicSharedMemorySize, SMEM_BYTES);
        configured = true;
    }

    prep_bfrag_kernel<<<128, 256>>>(W1);
    fused_mlp_kernel<<<2048, NTHREADS, SMEM_BYTES>>>(emb, idxg, idxd, b1, W2, b2, out);
}